// round 5
// baseline (speedup 1.0000x reference)
#include <cuda_runtime.h>

// Problem constants (from reference setup_inputs)
#define NB 8
#define NC 64
#define HH 128
#define WW 128
#define EH 64
#define EW 64
#define THETA 10.0f

#define CSPB 8                         // channels per block (apply kernel)
#define NCGRP (NC / CSPB)              // 8 channel groups
#define ROWS_PER_BLK 4                 // 4 warps -> 4 rows
#define NROWBLK (HH / ROWS_PER_BLK)    // 32
#define TBLK (ROWS_PER_BLK * 32)       // 128 threads

// Precomputed normalized weights: [n][y][k][x], k = 0..8 tap index.
// 8*128*9*128 floats = 4.72 MB (static device scratch; no runtime alloc).
__device__ float g_wbuf[NB * HH * 9 * WW];

// ---------------------------------------------------------------------------
// Kernel 1: per-pixel softmax weights from bilinear-upsampled edge.
// One warp per output row; each lane handles 4 pixels. Boundary zero-padding
// of the MASK taps is folded into the stored weights (padded tap * m=0 ==
// zero weight; softmax denominator already includes all 9 exps).
// ---------------------------------------------------------------------------
__global__ __launch_bounds__(TBLK)
void geg_weights_kernel(const float* __restrict__ edge)
{
    const int t    = threadIdx.x;
    const int warp = t >> 5;
    const int lane = t & 31;
    const int y    = blockIdx.x * ROWS_PER_BLK + warp;  // 0..127
    const int n    = blockIdx.y;                        // 0..7
    const int x0   = lane * 4;

    const float* eptr = edge + (size_t)n * (EH * EW);
    const float sc = 63.0f / 127.0f;   // (EH-1)/(HH-1), align_corners

    float er[3][6];
    #pragma unroll
    for (int r = 0; r < 3; r++) {
        const int gy = y - 1 + r;
        float4 ev = make_float4(0.f, 0.f, 0.f, 0.f);
        if (gy >= 0 && gy < HH) {
            const float ys = (float)gy * sc;
            const int   yi = (int)ys;
            const float wy = ys - (float)yi;
            const int   y1 = min(yi + 1, EH - 1);
            const float* r0 = eptr + yi * EW;
            const float* r1 = eptr + y1 * EW;
            float v[4];
            #pragma unroll
            for (int p = 0; p < 4; p++) {
                const int   gx = x0 + p;
                const float xs = (float)gx * sc;
                const int   xi = (int)xs;
                const float wx = xs - (float)xi;
                const int   x1 = min(xi + 1, EW - 1);
                const float a  = r0[xi];
                const float b  = r0[x1];
                const float c0 = r1[xi];
                const float d  = r1[x1];
                const float top = a  + (b  - a ) * wx;
                const float bot = c0 + (d  - c0) * wx;
                v[p] = top + (bot - top) * wy;
            }
            ev = make_float4(v[0], v[1], v[2], v[3]);
        }
        float left  = __shfl_up_sync(0xffffffffu, ev.w, 1);
        float right = __shfl_down_sync(0xffffffffu, ev.x, 1);
        if (lane == 0)  left  = 0.f;
        if (lane == 31) right = 0.f;
        er[r][0] = left; er[r][1] = ev.x; er[r][2] = ev.y;
        er[r][3] = ev.z; er[r][4] = ev.w; er[r][5] = right;
    }

    float w[4][9];
    #pragma unroll
    for (int p = 0; p < 4; p++) {
        const float ec = er[1][p + 1];
        float s = 0.f;
        #pragma unroll
        for (int k = 0; k < 9; k++) {
            const float d  = ec - er[k / 3][p + (k % 3)];
            const float pw = __expf(-THETA * d * d);
            w[p][k] = pw;
            s += pw;
        }
        const float rs = 1.f / s;
        #pragma unroll
        for (int k = 0; k < 9; k++) w[p][k] *= rs;
    }

    // Fold mask zero-padding into the weights.
    if (y == 0) {
        #pragma unroll
        for (int p = 0; p < 4; p++) { w[p][0] = 0.f; w[p][1] = 0.f; w[p][2] = 0.f; }
    }
    if (y == HH - 1) {
        #pragma unroll
        for (int p = 0; p < 4; p++) { w[p][6] = 0.f; w[p][7] = 0.f; w[p][8] = 0.f; }
    }
    if (lane == 0)  { w[0][0] = 0.f; w[0][3] = 0.f; w[0][6] = 0.f; }
    if (lane == 31) { w[3][2] = 0.f; w[3][5] = 0.f; w[3][8] = 0.f; }

    float* wb = g_wbuf + ((size_t)(n * HH + y) * 9) * WW + x0;
    #pragma unroll
    for (int k = 0; k < 9; k++)
        *reinterpret_cast<float4*>(wb + (size_t)k * WW) =
            make_float4(w[0][k], w[1][k], w[2][k], w[3][k]);
}

// ---------------------------------------------------------------------------
// Kernel 2: apply weights across channels. One warp per row; lane handles 4
// pixels; CSPB channels per block. Software-pipelined: channel c+1's loads
// are issued before channel c's compute, hiding L2 latency behind the body.
// ---------------------------------------------------------------------------
__global__ __launch_bounds__(TBLK, 5)
void geg_apply_kernel(const float* __restrict__ mask,
                      float* __restrict__ out)
{
    const int t    = threadIdx.x;
    const int warp = t >> 5;
    const int lane = t & 31;

    const int rowblk = blockIdx.x;     // 0..31
    const int cgrp   = blockIdx.y;     // 0..7
    const int n      = blockIdx.z;     // 0..7

    const int y  = rowblk * ROWS_PER_BLK + warp;
    const int x0 = lane * 4;

    const size_t img = (size_t)HH * WW;
    const float* mp = mask + ((size_t)n * NC + (size_t)cgrp * CSPB) * img;
    float*       op = out  + ((size_t)n * NC + (size_t)cgrp * CSPB) * img;

    // Clamped row offsets (OOB rows carry zero weight).
    const int off0 = max(y - 1, 0)      * WW + x0;
    const int off1 = y                  * WW + x0;
    const int off2 = min(y + 1, HH - 1) * WW + x0;
    const int offs = y * WW + x0;

    // Prologue loads for channel 0 — in flight while weights are fetched.
    float4 c0 = *reinterpret_cast<const float4*>(mp + off0);
    float4 c1 = *reinterpret_cast<const float4*>(mp + off1);
    float4 c2 = *reinterpret_cast<const float4*>(mp + off2);

    // Load the 36 precomputed weights (9 coalesced float4 loads).
    float w[4][9];
    {
        const float* wb = g_wbuf + ((size_t)(n * HH + y) * 9) * WW + x0;
        #pragma unroll
        for (int k = 0; k < 9; k++) {
            float4 v = *reinterpret_cast<const float4*>(wb + (size_t)k * WW);
            w[0][k] = v.x; w[1][k] = v.y; w[2][k] = v.z; w[3][k] = v.w;
        }
    }

    #pragma unroll 1
    for (int c = 0; c < CSPB; c++) {
        // Prefetch next channel (predicated off on the last iteration).
        const float* np = mp + img;
        float4 n0, n1, n2;
        if (c < CSPB - 1) {
            n0 = *reinterpret_cast<const float4*>(np + off0);
            n1 = *reinterpret_cast<const float4*>(np + off1);
            n2 = *reinterpret_cast<const float4*>(np + off2);
        }

        float mr[3][6];
        {
            float l0 = __shfl_up_sync(0xffffffffu, c0.w, 1);
            float r0 = __shfl_down_sync(0xffffffffu, c0.x, 1);
            float l1 = __shfl_up_sync(0xffffffffu, c1.w, 1);
            float r1 = __shfl_down_sync(0xffffffffu, c1.x, 1);
            float l2 = __shfl_up_sync(0xffffffffu, c2.w, 1);
            float r2 = __shfl_down_sync(0xffffffffu, c2.x, 1);
            mr[0][0]=l0; mr[0][1]=c0.x; mr[0][2]=c0.y; mr[0][3]=c0.z; mr[0][4]=c0.w; mr[0][5]=r0;
            mr[1][0]=l1; mr[1][1]=c1.x; mr[1][2]=c1.y; mr[1][3]=c1.z; mr[1][4]=c1.w; mr[1][5]=r1;
            mr[2][0]=l2; mr[2][1]=c2.x; mr[2][2]=c2.y; mr[2][3]=c2.z; mr[2][4]=c2.w; mr[2][5]=r2;
        }

        float a[4];
        #pragma unroll
        for (int p = 0; p < 4; p++) {
            float s = 0.f;
            #pragma unroll
            for (int k = 0; k < 9; k++)
                s = fmaf(w[p][k], mr[k / 3][p + (k % 3)], s);
            a[p] = s;
        }

        *reinterpret_cast<float4*>(op + offs) = make_float4(a[0], a[1], a[2], a[3]);

        c0 = n0; c1 = n1; c2 = n2;
        mp = np;
        op += img;
    }
}

extern "C" void kernel_launch(void* const* d_in, const int* in_sizes, int n_in,
                              void* d_out, int out_size)
{
    const float* mask = (const float*)d_in[0];
    const float* edge = (const float*)d_in[1];
    if (n_in >= 2 && in_sizes[0] < in_sizes[1]) {   // defensive swap by size
        const float* tmp = mask; mask = edge; edge = tmp;
    }
    float* out = (float*)d_out;

    dim3 wgrid(NROWBLK, NB);            // 32 x 8 = 256 blocks
    geg_weights_kernel<<<wgrid, TBLK>>>(edge);

    dim3 agrid(NROWBLK, NCGRP, NB);     // 32 x 8 x 8 = 2048 blocks
    geg_apply_kernel<<<agrid, TBLK>>>(mask, out);
}